// round 8
// baseline (speedup 1.0000x reference)
#include <cuda_runtime.h>
#include <cstdint>

#define BV     32
#define TT     2048
#define DD     512
#define MAXR   1024                 // true max runs in T=2048 (alternating)
#define NITEMS (BV * MAXR * 2)      // (video,run-slot,half) work items
#define GBLK   608                  // 152 SMs * 4
#define CTf    0.7f
#define CPTf   0.5f

// ---------------- device scratch (no allocations allowed) ----------------
// g_meta[b*1024+k] for k < g_nqual[b]: {as_int start, as_int len, 1/cnt, 1/rep}
// (compacted: qualifying runs only). All control words reset each launch.
__device__ float4 g_meta[BV * MAXR];
__device__ float  g_vid_attn[BV];
__device__ int    g_nqual[BV];
__device__ float  g_bsum[GBLK];
__device__ int    g_ready;          // videos analyzed (reset by last block)
__device__ int    g_done;           // blocks finished (reset by last block)

__global__ __launch_bounds__(256)
void fusedKernel(const float* __restrict__ attn,
                 const float* __restrict__ feat,
                 float* __restrict__ out)
{
    __shared__ float         s_attn[TT];          // 8 KB
    __shared__ unsigned char s_predB[256];
    __shared__ unsigned int  s_word[64];
    __shared__ int           s_scnt[64];
    __shared__ int           s_wbase[64];
    __shared__ int           s_total;
    __shared__ int           s_rstart[MAXR];
    __shared__ int           s_rlen[MAXR];
    __shared__ float         s_rmse[MAXR];
    __shared__ float         s_ric[MAXR];
    __shared__ float         s_rir[MAXR];
    __shared__ int           s_wTot[8];
    __shared__ float         s_red[8];
    __shared__ float         s_part[8];
    __shared__ int           s_isLast;

    const int tid  = threadIdx.x;
    const int lane = tid & 31;
    const int warp = tid >> 5;

    // ====================== phase 1: per-video analysis ======================
    if (blockIdx.x < BV) {
        const int b = blockIdx.x;
        const float* a_row = attn + (b << 11);

        const float4 v0 = ((const float4*)a_row)[tid * 2];
        const float4 v1 = ((const float4*)a_row)[tid * 2 + 1];
        ((float4*)s_attn)[tid * 2]     = v0;
        ((float4*)s_attn)[tid * 2 + 1] = v1;
        const float av[8] = {v0.x, v0.y, v0.z, v0.w, v1.x, v1.y, v1.z, v1.w};
        unsigned int byte = 0;
        #pragma unroll
        for (int j = 0; j < 8; j++) byte |= (av[j] > CPTf ? 1u : 0u) << j;
        s_predB[tid] = (unsigned char)byte;
        __syncthreads();

        unsigned int myStart = 0, myWord = 0;
        if (tid < 64) {
            myWord = (unsigned)s_predB[4*tid]
                   | ((unsigned)s_predB[4*tid+1] << 8)
                   | ((unsigned)s_predB[4*tid+2] << 16)
                   | ((unsigned)s_predB[4*tid+3] << 24);
            const unsigned carry = tid ? ((s_predB[4*tid - 1] >> 7) & 1u) : 0u;
            myStart = myWord & ~((myWord << 1) | carry);
            s_word[tid] = myWord;
            s_scnt[tid] = __popc(myStart);
        }
        __syncthreads();

        if (warp == 0) {                       // scan 64 word start-counts
            const int c0 = s_scnt[2*lane], c1 = s_scnt[2*lane+1];
            int incl = c0 + c1;
            #pragma unroll
            for (int o = 1; o < 32; o <<= 1) {
                int u = __shfl_up_sync(0xffffffffu, incl, o);
                if (lane >= o) incl += u;
            }
            const int excl = incl - (c0 + c1);
            s_wbase[2*lane]     = excl;
            s_wbase[2*lane + 1] = excl + c0;
            if (lane == 31) s_total = incl;
        }
        __syncthreads();

        // ---- run extraction: no atomics, bit-parallel ----
        if (tid < 64 && myStart) {
            int rbase = s_wbase[tid];
            unsigned sb = myStart;
            while (sb) {
                const int bit = __ffs(sb) - 1; sb &= sb - 1;
                const int t0 = tid * 32 + bit;
                int len = 0, ww = tid;
                unsigned cur = myWord >> bit;
                int avail = 32 - bit;
                while (true) {
                    const unsigned inv = ~cur;
                    int c = inv ? (__ffs(inv) - 1) : 32;
                    if (c > avail) c = avail;
                    len += c;
                    if (c < avail) break;
                    if (++ww >= 64) break;
                    cur = s_word[ww]; avail = 32;
                }
                float sum = 0.f; int rep = 0;
                for (int j = 0; j < len; j++) {
                    const float a = s_attn[t0 + j];
                    sum += a; rep += (a > CTf) ? 1 : 0;
                }
                const float mean = sum / (float)len;
                float ssq = 0.f;
                for (int j = 0; j < len; j++) {
                    const float d = s_attn[t0 + j] - mean;
                    ssq += d * d;
                }
                s_rstart[rbase] = t0;
                s_rlen[rbase]   = len;
                s_rmse[rbase]   = ssq / (float)len;
                s_ric[rbase]    = 1.0f / (float)len;
                s_rir[rbase]    = (rep > 0) ? (1.0f / (float)rep) : 0.0f;
                rbase++;
            }
        }
        __syncthreads();

        // ---- compact qualifying runs + attn-level reduction ----
        const int total = s_total;
        float attnAcc = 0.f;
        int q = 0;
        float4 ml[4];
        #pragma unroll
        for (int j = 0; j < 4; j++) {
            const int r = 4 * tid + j;
            if (r < total) {
                attnAcc += s_rmse[r];
                const float ir = s_rir[r];
                if (ir != 0.f) {
                    ml[q].x = __int_as_float(s_rstart[r]);
                    ml[q].y = __int_as_float(s_rlen[r]);
                    ml[q].z = s_ric[r];
                    ml[q].w = ir;
                    q++;
                }
            }
        }
        int incl = q;
        #pragma unroll
        for (int o = 1; o < 32; o <<= 1) {
            int u = __shfl_up_sync(0xffffffffu, incl, o);
            if (lane >= o) incl += u;
        }
        if (lane == 31) s_wTot[warp] = incl;
        float ar = attnAcc;
        #pragma unroll
        for (int o = 16; o > 0; o >>= 1) ar += __shfl_xor_sync(0xffffffffu, ar, o);
        if (lane == 0) s_red[warp] = ar;
        __syncthreads();
        if (tid == 0) {
            int acc = 0;
            #pragma unroll
            for (int w = 0; w < 8; w++) { const int v = s_wTot[w]; s_wTot[w] = acc; acc += v; }
            float asum = 0.f;
            #pragma unroll
            for (int w = 0; w < 8; w++) asum += s_red[w];
            g_vid_attn[b] = asum / (float)max(total, 1);
            g_nqual[b]    = acc;
        }
        __syncthreads();
        const int base = s_wTot[warp] + (incl - q);
        for (int j = 0; j < q; j++) g_meta[(b << 10) + base + j] = ml[j];

        __threadfence();
        __syncthreads();
        if (tid == 0) atomicAdd(&g_ready, 1);
    }

    // ====================== phase 2: wait for all metadata ===================
    if (tid == 0) {
        while (atomicAdd(&g_ready, 0) < BV) __nanosleep(64);
    }
    __syncthreads();
    __threadfence();

    // ====================== phase 3: feat streaming ==========================
    // item i: b = i>>11, k = (i>>1)&1023 (compacted qual run), half = i&1
    const int gwarp  = blockIdx.x * 8 + warp;
    const int stride = gridDim.x * 8;
    float bsum = 0.f;

    int i = gwarp;
    float4 m = make_float4(0.f, 0.f, 0.f, 0.f);
    int b = 0, half = 0; bool act = false;
    if (i < NITEMS) {
        b = i >> 11; const int k = (i >> 1) & 1023; half = i & 1;
        m = g_meta[(b << 10) + k];
        act = (k < g_nqual[b]);
    }
    while (i < NITEMS) {
        const int in = i + stride;
        float4 mn = make_float4(0.f, 0.f, 0.f, 0.f);
        int bn = 0, hn = 0; bool actn = false;
        if (in < NITEMS) {                       // prefetch next item's meta
            bn = in >> 11; const int kn = (in >> 1) & 1023; hn = in & 1;
            mn = g_meta[(bn << 10) + kn];
            actn = (kn < g_nqual[bn]);
        }
        if (act) {
            const int   s  = __float_as_int(m.x);
            const int   L  = __float_as_int(m.y);
            const float ic = m.z;
            const float ir = m.w;
            const float* arow = attn + (b << 11) + s;
            const float4* basep = ((const float4*)feat)
                                + ((size_t)((b << 11) + s)) * (DD / 4)
                                + (half << 6) + lane;
            float4 A  = make_float4(0.f, 0.f, 0.f, 0.f);
            float4 Bv = A;
            int t = 0;
            for (; t + 2 <= L; t += 2) {
                const float a0 = __ldg(arow + t);
                const float a1 = __ldg(arow + t + 1);
                const float4* r0 = basep + (size_t)t * (DD / 4);
                const float4* r1 = r0 + (DD / 4);
                const float4 f0 = __ldg(r0), f1 = __ldg(r0 + 32);
                const float4 h0 = __ldg(r1), h1 = __ldg(r1 + 32);
                const float c0 = ic - ((a0 > CTf) ? ir : 0.f);
                const float c1 = ic - ((a1 > CTf) ? ir : 0.f);
                A.x  += c0*f0.x + c1*h0.x;  A.y  += c0*f0.y + c1*h0.y;
                A.z  += c0*f0.z + c1*h0.z;  A.w  += c0*f0.w + c1*h0.w;
                Bv.x += c0*f1.x + c1*h1.x;  Bv.y += c0*f1.y + c1*h1.y;
                Bv.z += c0*f1.z + c1*h1.z;  Bv.w += c0*f1.w + c1*h1.w;
            }
            if (t < L) {
                const float a0 = __ldg(arow + t);
                const float4* r0 = basep + (size_t)t * (DD / 4);
                const float4 f0 = __ldg(r0), f1 = __ldg(r0 + 32);
                const float c0 = ic - ((a0 > CTf) ? ir : 0.f);
                A.x  += c0*f0.x; A.y  += c0*f0.y; A.z  += c0*f0.z; A.w  += c0*f0.w;
                Bv.x += c0*f1.x; Bv.y += c0*f1.y; Bv.z += c0*f1.z; Bv.w += c0*f1.w;
            }
            bsum += A.x*A.x + A.y*A.y + A.z*A.z + A.w*A.w
                  + Bv.x*Bv.x + Bv.y*Bv.y + Bv.z*Bv.z + Bv.w*Bv.w;
        }
        i = in; m = mn; b = bn; half = hn; act = actn;
    }

    // block partial
    #pragma unroll
    for (int o = 16; o > 0; o >>= 1) bsum += __shfl_xor_sync(0xffffffffu, bsum, o);
    if (lane == 0) s_part[warp] = bsum;
    __syncthreads();
    if (tid == 0) {
        float tot = 0.f;
        #pragma unroll
        for (int w = 0; w < 8; w++) tot += s_part[w];
        g_bsum[blockIdx.x] = tot;
        __threadfence();
        const int old = atomicAdd(&g_done, 1);
        s_isLast = (old == (int)gridDim.x - 1) ? 1 : 0;
    }
    __syncthreads();

    // ====================== phase 4: last block finalizes ====================
    if (s_isLast) {
        __threadfence();
        float acc = 0.f;
        for (int j = tid; j < GBLK; j += 256) acc += g_bsum[j];
        #pragma unroll
        for (int o = 16; o > 0; o >>= 1) acc += __shfl_xor_sync(0xffffffffu, acc, o);
        if (lane == 0) s_red[warp] = acc;
        __syncthreads();
        if (tid == 0) {
            float f = 0.f;
            #pragma unroll
            for (int w = 0; w < 8; w++) f += s_red[w];
            float asum = 0.f; int qs = 0;
            #pragma unroll
            for (int v = 0; v < BV; v++) { asum += g_vid_attn[v]; qs += g_nqual[v]; }
            const float feat_loss = (f * (1.0f / (float)DD)) / (float)max(qs, 1);
            const float attn_loss = asum / (float)BV;
            out[0] = feat_loss + attn_loss;     // FW = AW = 1
            g_done  = 0;                        // reset for next graph replay
            g_ready = 0;
        }
    }
}

// ============================================================================
extern "C" void kernel_launch(void* const* d_in, const int* in_sizes, int n_in,
                              void* d_out, int out_size)
{
    const float* attn = (const float*)d_in[0];
    const float* feat = (const float*)d_in[1];
    if (n_in >= 2 && in_sizes[0] > in_sizes[1]) {
        const float* tmp = attn; attn = feat; feat = tmp;
    }
    fusedKernel<<<GBLK, 256>>>(attn, feat, (float*)d_out);
}